// round 1
// baseline (speedup 1.0000x reference)
#include <cuda_runtime.h>
#include <math.h>

#define B_N 1024
#define F_N 257
#define BF_N (B_N * F_N)          // 263168
#define NCONVBLK (BF_N / 64)      // 4112
#define NTOKBLK (BF_N / 256)      // 1028

// -------- device scratch (allocation-free; __device__ globals) --------
__device__ __align__(16) float g_h[2][(size_t)BF_N * 32];  // ping-pong activations
__device__ __align__(16) float g_c[(size_t)BF_N * 32];     // conv output scratch
__device__ __align__(16) float g_part[NCONVBLK][64];       // BN partial sums (sum | sumsq)
__device__ __align__(16) float g_bn[2][32];                // per-channel scale / shift

__device__ __forceinline__ float gelu_f(float x) {
    // exact GELU: x * 0.5 * (1 + erf(x / sqrt(2)))
    return 0.5f * x * (1.0f + erff(x * 0.70710678118654752440f));
}

// ===================== input projection: (B,F,18) @ (18,32) =====================
__global__ __launch_bounds__(256) void k_inproj(const float* __restrict__ x,
                                                const float* __restrict__ in_w,
                                                const float* __restrict__ in_b) {
    __shared__ __align__(16) float xs[256][19];
    __shared__ __align__(16) float ws[18 * 32];
    __shared__ float bs[32];
    int t0 = blockIdx.x * 256;
    for (int idx = threadIdx.x; idx < 256 * 18; idx += 256) {
        int tok = idx / 18, i = idx - tok * 18;
        xs[tok][i] = x[(size_t)t0 * 18 + idx];  // tokens contiguous -> fully coalesced
    }
    for (int idx = threadIdx.x; idx < 18 * 32; idx += 256) ws[idx] = in_w[idx];
    if (threadIdx.x < 32) bs[threadIdx.x] = in_b[threadIdx.x];
    __syncthreads();

    int tok = threadIdx.x;
    float acc[32];
#pragma unroll
    for (int c = 0; c < 32; c++) acc[c] = bs[c];
#pragma unroll
    for (int i = 0; i < 18; i++) {
        float a = xs[tok][i];
#pragma unroll
        for (int c = 0; c < 32; c++) acc[c] += a * ws[i * 32 + c];  // ws uniform -> LDS broadcast
    }
    float4* o = reinterpret_cast<float4*>(&g_h[0][((size_t)(t0 + tok)) * 32]);
#pragma unroll
    for (int k = 0; k < 8; k++)
        o[k] = make_float4(acc[4 * k], acc[4 * k + 1], acc[4 * k + 2], acc[4 * k + 3]);
}

// ===================== conv (width 3, SAME, over F) + BN partial stats =====================
__global__ __launch_bounds__(256) void k_conv(const float* __restrict__ cw, int src) {
    __shared__ __align__(16) float hs[66][36];   // tokens g0-1 .. g0+64, padded rows
    __shared__ __align__(16) float ws[3072];     // (3,32,32) = (w, in, out)
    __shared__ float red[8][4][8][2];            // [warp][slot][j][sum/sumsq]
    const float* hsrc = g_h[src];
    int g0 = blockIdx.x * 64;

    for (int idx = threadIdx.x; idx < 66 * 32; idx += 256) {
        int r = idx >> 5, c = idx & 31;
        long tg = (long)g0 - 1 + r;
        hs[r][c] = (tg >= 0 && tg < BF_N) ? hsrc[(size_t)tg * 32 + c] : 0.f;
    }
    for (int idx = threadIdx.x; idx < 3072; idx += 256) ws[idx] = cw[idx];
    __syncthreads();

    int tl = threadIdx.x >> 2, o0 = (threadIdx.x & 3) << 3;
    int g = g0 + tl, f = g % F_N;
    float acc[8] = {0.f, 0.f, 0.f, 0.f, 0.f, 0.f, 0.f, 0.f};
#pragma unroll
    for (int w = 0; w < 3; w++) {
        // SAME zero-padding at the frequency-row edges (mask at use time)
        if (w == 0 && f == 0) continue;
        if (w == 2 && f == F_N - 1) continue;
        const float* hr = hs[tl + w];
        const float* wb = ws + w * 1024 + o0;
#pragma unroll
        for (int i = 0; i < 32; i++) {
            float a = hr[i];
            float4 w0 = *reinterpret_cast<const float4*>(wb + i * 32);
            float4 w1 = *reinterpret_cast<const float4*>(wb + i * 32 + 4);
            acc[0] += a * w0.x; acc[1] += a * w0.y; acc[2] += a * w0.z; acc[3] += a * w0.w;
            acc[4] += a * w1.x; acc[5] += a * w1.y; acc[6] += a * w1.z; acc[7] += a * w1.w;
        }
    }

    float4* co = reinterpret_cast<float4*>(&g_c[(size_t)g * 32 + o0]);
    co[0] = make_float4(acc[0], acc[1], acc[2], acc[3]);
    co[1] = make_float4(acc[4], acc[5], acc[6], acc[7]);

    // deterministic stats reduction: shuffle over the 8 tokens in the warp
    float s1[8], s2[8];
#pragma unroll
    for (int j = 0; j < 8; j++) { s1[j] = acc[j]; s2[j] = acc[j] * acc[j]; }
#pragma unroll
    for (int off = 4; off < 32; off <<= 1) {
#pragma unroll
        for (int j = 0; j < 8; j++) {
            s1[j] += __shfl_xor_sync(0xffffffffu, s1[j], off);
            s2[j] += __shfl_xor_sync(0xffffffffu, s2[j], off);
        }
    }
    int warp = threadIdx.x >> 5, lane = threadIdx.x & 31;
    if (lane < 4) {
#pragma unroll
        for (int j = 0; j < 8; j++) { red[warp][lane][j][0] = s1[j]; red[warp][lane][j][1] = s2[j]; }
    }
    __syncthreads();
    if (threadIdx.x < 64) {
        int kind = threadIdx.x >> 5, ch = threadIdx.x & 31;
        int sl = ch >> 3, j = ch & 7;
        float v = 0.f;
#pragma unroll
        for (int w2 = 0; w2 < 8; w2++) v += red[w2][sl][j][kind];
        g_part[blockIdx.x][kind * 32 + ch] = v;
    }
}

// ===================== BN finalize: one block per channel =====================
__global__ __launch_bounds__(256) void k_bnfin(const float* __restrict__ bng,
                                               const float* __restrict__ bnb) {
    __shared__ float rs[256], rq[256];
    int c = blockIdx.x;
    float s = 0.f, q = 0.f;
    for (int i = threadIdx.x; i < NCONVBLK; i += 256) {
        s += g_part[i][c];
        q += g_part[i][32 + c];
    }
    rs[threadIdx.x] = s; rq[threadIdx.x] = q;
    __syncthreads();
    for (int off = 128; off > 0; off >>= 1) {
        if (threadIdx.x < off) {
            rs[threadIdx.x] += rs[threadIdx.x + off];
            rq[threadIdx.x] += rq[threadIdx.x + off];
        }
        __syncthreads();
    }
    if (threadIdx.x == 0) {
        float mean = rs[0] * (1.0f / BF_N);
        float var = rq[0] * (1.0f / BF_N) - mean * mean;  // biased
        float a = rsqrtf(var + 1e-5f) * bng[c];
        g_bn[0][c] = a;
        g_bn[1][c] = bnb[c] - mean * a;
    }
}

// ===================== fused qkv GEMM + banded attention + proj + BN/GELU path + LayerNorm =====================
__global__ __launch_bounds__(256) void k_apply(const float* __restrict__ qw,
                                               const float* __restrict__ pw,
                                               const float* __restrict__ pbias,
                                               const float* __restrict__ lng,
                                               const float* __restrict__ lnb,
                                               int src) {
    extern __shared__ float sm[];
    float* ht  = sm;               // [32][68] transposed h tile (reused as y tile later)
    float* qs  = ht + 32 * 68;     // [96][68] qkv, column-major over tokens
    float* as_ = qs + 96 * 68;     // [32][68] attention output (pre-proj)
    float* wq  = as_ + 32 * 68;    // 32x96
    float* wp  = wq + 3072;        // 32x32
    float* pb  = wp + 1024;
    float* lg  = pb + 32;
    float* lb  = lg + 32;
    float* bna = lb + 32;
    float* bnb = bna + 32;

    const float* hsrc = g_h[src];
    float* hdst = g_h[src ^ 1];
    int fb = blockIdx.x * 64;
    size_t rowbase = (size_t)blockIdx.y * F_N;
    int tid = threadIdx.x;

    // stage h (transposed), weights, per-layer params
    for (int idx = tid; idx < 68 * 32; idx += 256) {
        int t = idx >> 5, c = idx & 31;
        float v = (fb + t < F_N) ? hsrc[(rowbase + fb + t) * 32 + c] : 0.f;
        ht[c * 68 + t] = v;
    }
    for (int idx = tid; idx < 3072; idx += 256) wq[idx] = qw[idx];
    for (int idx = tid; idx < 1024; idx += 256) wp[idx] = pw[idx];
    if (tid < 32) {
        pb[tid] = pbias[tid]; lg[tid] = lng[tid]; lb[tid] = lnb[tid];
        bna[tid] = g_bn[0][tid]; bnb[tid] = g_bn[1][tid];
    }
    __syncthreads();

    // ---- Phase B: qkv GEMM (68 tokens x 96 out, K=32), 4x8 register tile ----
    if (tid < 204) {
        int og = tid / 17, tg = tid - og * 17;
        int t0 = tg * 4, oc = og * 8;
        float acc[4][8];
#pragma unroll
        for (int a = 0; a < 4; a++)
#pragma unroll
            for (int b = 0; b < 8; b++) acc[a][b] = 0.f;
#pragma unroll
        for (int i = 0; i < 32; i++) {
            float4 av = *reinterpret_cast<const float4*>(&ht[i * 68 + t0]);
            float4 w0 = *reinterpret_cast<const float4*>(&wq[i * 96 + oc]);
            float4 w1 = *reinterpret_cast<const float4*>(&wq[i * 96 + oc + 4]);
            float wv[8] = {w0.x, w0.y, w0.z, w0.w, w1.x, w1.y, w1.z, w1.w};
            float avv[4] = {av.x, av.y, av.z, av.w};
#pragma unroll
            for (int a = 0; a < 4; a++)
#pragma unroll
                for (int b = 0; b < 8; b++) acc[a][b] += avv[a] * wv[b];
        }
#pragma unroll
        for (int b = 0; b < 8; b++)
            *reinterpret_cast<float4*>(&qs[(oc + b) * 68 + t0]) =
                make_float4(acc[0][b], acc[1][b], acc[2][b], acc[3][b]);
    }
    __syncthreads();

    // ---- Phase C: banded attention, warp per token, lane = channel ----
    int warp = tid >> 5, lane = tid & 31;
    for (int rep = 0; rep < 8; rep++) {
        int tl = rep * 8 + warp;
        int f = fb + tl;
        float ao = 0.f;
        if (f < F_N) {
            float qv = qs[lane * 68 + tl];
            float s[3];
#pragma unroll
            for (int j = 0; j < 3; j++) {
                float p = qv * qs[(32 + lane) * 68 + tl + j];
                p += __shfl_xor_sync(0xffffffffu, p, 1);   // reduce over d within the
                p += __shfl_xor_sync(0xffffffffu, p, 2);   // 8-lane head octet
                p += __shfl_xor_sync(0xffffffffu, p, 4);
                s[j] = (f + j < F_N) ? p * 0.35355339059327373f : -INFINITY;
            }
            float m = fmaxf(s[0], fmaxf(s[1], s[2]));
            float e0 = __expf(s[0] - m);
            float e1 = (f + 1 < F_N) ? __expf(s[1] - m) : 0.f;
            float e2 = (f + 2 < F_N) ? __expf(s[2] - m) : 0.f;
            float inv = 1.f / (e0 + e1 + e2);
            ao = (e0 * qs[(64 + lane) * 68 + tl]
                + e1 * qs[(64 + lane) * 68 + tl + 1]
                + e2 * qs[(64 + lane) * 68 + tl + 2]) * inv;
        }
        as_[lane * 68 + tl] = ao;
    }
    __syncthreads();

    // ---- Phase D: proj GEMM + BN/GELU conv path; y -> ht (reused) ----
    {
        int tl = tid >> 2, o0 = (tid & 3) << 3;
        int f = fb + tl;
        if (f < F_N) {
            float acc[8];
#pragma unroll
            for (int j = 0; j < 8; j++) acc[j] = pb[o0 + j];
#pragma unroll
            for (int i = 0; i < 32; i++) {
                float a = as_[i * 68 + tl];
                float4 w0 = *reinterpret_cast<const float4*>(&wp[i * 32 + o0]);
                float4 w1 = *reinterpret_cast<const float4*>(&wp[i * 32 + o0 + 4]);
                acc[0] += a * w0.x; acc[1] += a * w0.y; acc[2] += a * w0.z; acc[3] += a * w0.w;
                acc[4] += a * w1.x; acc[5] += a * w1.y; acc[6] += a * w1.z; acc[7] += a * w1.w;
            }
            const float4* cg = reinterpret_cast<const float4*>(&g_c[(rowbase + f) * 32 + o0]);
            float4 c0 = cg[0], c1 = cg[1];
            float cv[8] = {c0.x, c0.y, c0.z, c0.w, c1.x, c1.y, c1.z, c1.w};
#pragma unroll
            for (int j = 0; j < 8; j++) {
                float cn = cv[j] * bna[o0 + j] + bnb[o0 + j];
                ht[(o0 + j) * 68 + tl] = gelu_f(cn) + acc[j];
            }
        }
    }
    __syncthreads();

    // ---- Phase E: LayerNorm over channels, warp per token ----
    for (int rep = 0; rep < 8; rep++) {
        int tl = rep * 8 + warp;
        int f = fb + tl;
        if (f < F_N) {
            float y = ht[lane * 68 + tl];
            float s = y;
#pragma unroll
            for (int off = 1; off < 32; off <<= 1) s += __shfl_xor_sync(0xffffffffu, s, off);
            float mean = s * (1.f / 32.f);
            float d = y - mean;
            float v = d * d;
#pragma unroll
            for (int off = 1; off < 32; off <<= 1) v += __shfl_xor_sync(0xffffffffu, v, off);
            float o = d * rsqrtf(v * (1.f / 32.f) + 1e-5f) * lg[lane] + lb[lane];
            hdst[(rowbase + f) * 32 + lane] = o;
        }
    }
}

// ===================== head: gelu(h@W1+b1) @ W2 + b2 -> sigmoid =====================
__global__ __launch_bounds__(256) void k_head(const float* __restrict__ w1,
                                              const float* __restrict__ b1,
                                              const float* __restrict__ w2,
                                              const float* __restrict__ b2,
                                              float* __restrict__ out) {
    __shared__ __align__(16) float hsm[256][33];
    __shared__ float ws1[512];
    __shared__ float wb1[16], ws2[16];
    __shared__ float b2s;
    int t0 = blockIdx.x * 256;
    const float* hsrc = g_h[0];
    for (int idx = threadIdx.x; idx < 256 * 32; idx += 256) {
        int tok = idx >> 5, c = idx & 31;
        hsm[tok][c] = hsrc[(size_t)(t0 + tok) * 32 + c];
    }
    for (int idx = threadIdx.x; idx < 512; idx += 256) ws1[idx] = w1[idx];
    if (threadIdx.x < 16) { wb1[threadIdx.x] = b1[threadIdx.x]; ws2[threadIdx.x] = w2[threadIdx.x]; }
    if (threadIdx.x == 0) b2s = b2[0];
    __syncthreads();

    const float* hr = hsm[threadIdx.x];
    float s[16];
#pragma unroll
    for (int j = 0; j < 16; j++) s[j] = wb1[j];
#pragma unroll
    for (int i = 0; i < 32; i++) {
        float a = hr[i];
#pragma unroll
        for (int j = 0; j < 16; j++) s[j] += a * ws1[i * 16 + j];  // broadcast weights
    }
    float m = b2s;
#pragma unroll
    for (int j = 0; j < 16; j++) m += gelu_f(s[j]) * ws2[j];
    out[t0 + threadIdx.x] = 1.f / (1.f + expf(-m));
}

// ===================== launcher =====================
extern "C" void kernel_launch(void* const* d_in, const int* in_sizes, int n_in,
                              void* d_out, int out_size) {
    const float* x      = (const float*)d_in[0];
    const float* in_w   = (const float*)d_in[1];
    const float* in_b   = (const float*)d_in[2];
    const float* conv_w = (const float*)d_in[3];
    const float* bn_g   = (const float*)d_in[4];
    const float* bn_b   = (const float*)d_in[5];
    const float* qkv_w  = (const float*)d_in[6];
    const float* proj_w = (const float*)d_in[7];
    const float* proj_b = (const float*)d_in[8];
    const float* ln_g   = (const float*)d_in[9];
    const float* ln_b   = (const float*)d_in[10];
    const float* h1_w   = (const float*)d_in[11];
    const float* h1_b   = (const float*)d_in[12];
    const float* h2_w   = (const float*)d_in[13];
    const float* h2_b   = (const float*)d_in[14];
    float* out = (float*)d_out;

    const int smem_apply = (32 * 68 + 96 * 68 + 32 * 68 + 3072 + 1024 + 32 * 5) * (int)sizeof(float);
    cudaFuncSetAttribute(k_apply, cudaFuncAttributeMaxDynamicSharedMemorySize, smem_apply);

    k_inproj<<<NTOKBLK, 256>>>(x, in_w, in_b);
    for (int l = 0; l < 4; l++) {
        int src = l & 1;  // inproj wrote g_h[0]; ping-pong each layer
        k_conv<<<NCONVBLK, 256>>>(conv_w + l * 3072, src);
        k_bnfin<<<32, 256>>>(bn_g + l * 32, bn_b + l * 32);
        k_apply<<<dim3(5, 1024), 256, smem_apply>>>(qkv_w + l * 3072, proj_w + l * 1024,
                                                    proj_b + l * 32, ln_g + l * 32,
                                                    ln_b + l * 32, src);
    }
    k_head<<<NTOKBLK, 256>>>(h1_w, h1_b, h2_w, h2_b, out);
}

// round 2
// speedup vs baseline: 1.1134x; 1.1134x over previous
#include <cuda_runtime.h>
#include <math.h>

#define B_N 1024
#define F_N 257
#define BF_N (B_N * F_N)          // 263168
#define NCONVBLK (BF_N / 64)      // 4112
#define NTOKBLK (BF_N / 256)      // 1028
#define T_TILE 65                 // tokens per apply block (4 tiles cover F=257)

typedef unsigned long long u64;

// -------- device scratch (allocation-free; __device__ globals) --------
__device__ __align__(16) float g_h[2][(size_t)BF_N * 32];  // ping-pong activations
__device__ __align__(16) float g_c[(size_t)BF_N * 32];     // conv output scratch
__device__ __align__(16) float g_part[NCONVBLK][64];       // BN partial sums (sum | sumsq)
__device__ __align__(16) float g_bn[2][32];                // per-channel scale / shift

__device__ __forceinline__ float gelu_f(float x) {
    return 0.5f * x * (1.0f + erff(x * 0.70710678118654752440f));
}

// packed f32x2 FMA (Blackwell FFMA2): d = a * b + d, per 32-bit lane
__device__ __forceinline__ void ffma2(u64& d, u64 a, u64 b) {
    asm("fma.rn.f32x2 %0, %1, %2, %0;" : "+l"(d) : "l"(a), "l"(b));
}
__device__ __forceinline__ u64 pack2(float x) {
    u64 r; asm("mov.b64 %0, {%1, %1};" : "=l"(r) : "f"(x)); return r;
}
__device__ __forceinline__ float2 unpack2(u64 a) {
    float2 f; asm("mov.b64 {%0, %1}, %2;" : "=f"(f.x), "=f"(f.y) : "l"(a)); return f;
}

// ===================== input projection: (B,F,18) @ (18,32) =====================
__global__ __launch_bounds__(256) void k_inproj(const float* __restrict__ x,
                                                const float* __restrict__ in_w,
                                                const float* __restrict__ in_b) {
    __shared__ __align__(16) float xs[256][19];
    __shared__ __align__(16) float ws[18 * 32];
    __shared__ __align__(16) float bs[32];
    int t0 = blockIdx.x * 256;
    for (int idx = threadIdx.x; idx < 256 * 18; idx += 256) {
        int tok = idx / 18, i = idx - tok * 18;
        xs[tok][i] = x[(size_t)t0 * 18 + idx];
    }
    for (int idx = threadIdx.x; idx < 18 * 32; idx += 256) ws[idx] = in_w[idx];
    if (threadIdx.x < 32) bs[threadIdx.x] = in_b[threadIdx.x];
    __syncthreads();

    int tok = threadIdx.x;
    u64 acc[16];
    const u64* bs2 = reinterpret_cast<const u64*>(bs);
#pragma unroll
    for (int k = 0; k < 16; k++) acc[k] = bs2[k];
#pragma unroll
    for (int i = 0; i < 18; i++) {
        u64 a2 = pack2(xs[tok][i]);
        const u64* wr = reinterpret_cast<const u64*>(ws + i * 32);
#pragma unroll
        for (int k = 0; k < 16; k++) ffma2(acc[k], a2, wr[k]);
    }
    ulonglong2* o = reinterpret_cast<ulonglong2*>(&g_h[0][((size_t)(t0 + tok)) * 32]);
#pragma unroll
    for (int k = 0; k < 8; k++) o[k] = make_ulonglong2(acc[2 * k], acc[2 * k + 1]);
}

// ===================== conv (width 3, SAME, over F) + BN partial stats =====================
__global__ __launch_bounds__(256) void k_conv(const float* __restrict__ cw, int src) {
    __shared__ __align__(16) float hs[66][36];
    __shared__ __align__(16) float ws[3072];     // (3,32,32) = (w, in, out)
    __shared__ float red[8][4][8][2];
    const float* hsrc = g_h[src];
    int g0 = blockIdx.x * 64;

    for (int idx = threadIdx.x; idx < 66 * 32; idx += 256) {
        int r = idx >> 5, c = idx & 31;
        long tg = (long)g0 - 1 + r;
        hs[r][c] = (tg >= 0 && tg < BF_N) ? hsrc[(size_t)tg * 32 + c] : 0.f;
    }
    for (int idx = threadIdx.x; idx < 3072; idx += 256) ws[idx] = cw[idx];
    __syncthreads();

    int tl = threadIdx.x >> 2, o0 = (threadIdx.x & 3) << 3;
    int g = g0 + tl, f = g % F_N;
    u64 acc2[4] = {0ull, 0ull, 0ull, 0ull};
#pragma unroll
    for (int w = 0; w < 3; w++) {
        if (w == 0 && f == 0) continue;
        if (w == 2 && f == F_N - 1) continue;
        const float* hr = hs[tl + w];
        const float* wb = ws + w * 1024 + o0;
#pragma unroll
        for (int i = 0; i < 32; i++) {
            u64 a2 = pack2(hr[i]);
            const u64* wr = reinterpret_cast<const u64*>(wb + i * 32);
            ffma2(acc2[0], a2, wr[0]);
            ffma2(acc2[1], a2, wr[1]);
            ffma2(acc2[2], a2, wr[2]);
            ffma2(acc2[3], a2, wr[3]);
        }
    }
    float acc[8];
#pragma unroll
    for (int k = 0; k < 4; k++) { float2 f2 = unpack2(acc2[k]); acc[2 * k] = f2.x; acc[2 * k + 1] = f2.y; }

    ulonglong2* co = reinterpret_cast<ulonglong2*>(&g_c[(size_t)g * 32 + o0]);
    co[0] = make_ulonglong2(acc2[0], acc2[1]);
    co[1] = make_ulonglong2(acc2[2], acc2[3]);

    float s1[8], s2[8];
#pragma unroll
    for (int j = 0; j < 8; j++) { s1[j] = acc[j]; s2[j] = acc[j] * acc[j]; }
#pragma unroll
    for (int off = 4; off < 32; off <<= 1) {
#pragma unroll
        for (int j = 0; j < 8; j++) {
            s1[j] += __shfl_xor_sync(0xffffffffu, s1[j], off);
            s2[j] += __shfl_xor_sync(0xffffffffu, s2[j], off);
        }
    }
    int warp = threadIdx.x >> 5, lane = threadIdx.x & 31;
    if (lane < 4) {
#pragma unroll
        for (int j = 0; j < 8; j++) { red[warp][lane][j][0] = s1[j]; red[warp][lane][j][1] = s2[j]; }
    }
    __syncthreads();
    if (threadIdx.x < 64) {
        int kind = threadIdx.x >> 5, ch = threadIdx.x & 31;
        int sl = ch >> 3, j = ch & 7;
        float v = 0.f;
#pragma unroll
        for (int w2 = 0; w2 < 8; w2++) v += red[w2][sl][j][kind];
        g_part[blockIdx.x][kind * 32 + ch] = v;
    }
}

// ===================== BN finalize: one block per channel =====================
__global__ __launch_bounds__(256) void k_bnfin(const float* __restrict__ bng,
                                               const float* __restrict__ bnb) {
    __shared__ float rs[256], rq[256];
    int c = blockIdx.x;
    float s = 0.f, q = 0.f;
    for (int i = threadIdx.x; i < NCONVBLK; i += 256) {
        s += g_part[i][c];
        q += g_part[i][32 + c];
    }
    rs[threadIdx.x] = s; rq[threadIdx.x] = q;
    __syncthreads();
    for (int off = 128; off > 0; off >>= 1) {
        if (threadIdx.x < off) {
            rs[threadIdx.x] += rs[threadIdx.x + off];
            rq[threadIdx.x] += rq[threadIdx.x + off];
        }
        __syncthreads();
    }
    if (threadIdx.x == 0) {
        float mean = rs[0] * (1.0f / BF_N);
        float var = rq[0] * (1.0f / BF_N) - mean * mean;
        float a = rsqrtf(var + 1e-5f) * bng[c];
        g_bn[0][c] = a;
        g_bn[1][c] = bnb[c] - mean * a;
    }
}

// ===================== fused qkv + banded attention + proj + BN/GELU + LayerNorm =====================
// smem map (floats):
//   [0, 2244)        ht channel-major [32][68] (first 2176) -> later as_ token-major [68][33]
//   [2244, 9044)     qs token-major [68][100] (q|k|v) -> later y token-major [68][36]
//   [9044, 12116)    wq 32x96
//   [12116, 13140)   wp 32x32
//   [13140, 13300)   pb, lg, lb, bna, bnb (32 each)
#define SMEM_APPLY_FLOATS 13300
__global__ __launch_bounds__(256) void k_apply(const float* __restrict__ qw,
                                               const float* __restrict__ pw,
                                               const float* __restrict__ pbias,
                                               const float* __restrict__ lng,
                                               const float* __restrict__ lnb,
                                               int src) {
    extern __shared__ float sm[];
    float* ht  = sm;                // [32][68] channel-major
    float* as_ = sm;                // [68][33] token-major (after Phase B)
    float* qs  = sm + 2244;         // [68][100] token-major
    float* y   = sm + 2244;         // [68][36] token-major (after Phase C)
    float* wq  = sm + 9044;
    float* wp  = wq + 3072;
    float* pb  = wp + 1024;
    float* lg  = pb + 32;
    float* lb  = lg + 32;
    float* bna = lb + 32;
    float* bnb = bna + 32;

    const float* hsrc = g_h[src];
    float* hdst = g_h[src ^ 1];
    int fb = blockIdx.x * T_TILE;
    size_t rowbase = (size_t)blockIdx.y * F_N;
    int tid = threadIdx.x;

    // stage h (transposed to channel-major), weights, per-layer params
    for (int idx = tid; idx < 68 * 32; idx += 256) {
        int t = idx >> 5, c = idx & 31;
        float v = (fb + t < F_N) ? hsrc[(rowbase + fb + t) * 32 + c] : 0.f;
        ht[c * 68 + t] = v;
    }
    for (int idx = tid; idx < 3072; idx += 256) wq[idx] = qw[idx];
    for (int idx = tid; idx < 1024; idx += 256) wp[idx] = pw[idx];
    if (tid < 32) {
        pb[tid] = pbias[tid]; lg[tid] = lng[tid]; lb[tid] = lnb[tid];
        bna[tid] = g_bn[0][tid]; bnb[tid] = g_bn[1][tid];
    }
    __syncthreads();

    // ---- Phase B: qkv GEMM (68 tokens x 96 out, K=32), 4 tok x 8 ch per thread, FFMA2 ----
    if (tid < 204) {
        int og = tid / 17, tg = tid - og * 17;
        int t0 = tg * 4, oc = og * 8;
        u64 acc2[4][4];
#pragma unroll
        for (int a = 0; a < 4; a++)
#pragma unroll
            for (int k = 0; k < 4; k++) acc2[a][k] = 0ull;
#pragma unroll
        for (int i = 0; i < 32; i++) {
            float4 av = *reinterpret_cast<const float4*>(&ht[i * 68 + t0]);
            const u64* wr = reinterpret_cast<const u64*>(&wq[i * 96 + oc]);
            u64 w0 = wr[0], w1 = wr[1], w2 = wr[2], w3 = wr[3];
            u64 a0 = pack2(av.x), a1 = pack2(av.y), a2 = pack2(av.z), a3 = pack2(av.w);
            ffma2(acc2[0][0], a0, w0); ffma2(acc2[0][1], a0, w1); ffma2(acc2[0][2], a0, w2); ffma2(acc2[0][3], a0, w3);
            ffma2(acc2[1][0], a1, w0); ffma2(acc2[1][1], a1, w1); ffma2(acc2[1][2], a1, w2); ffma2(acc2[1][3], a1, w3);
            ffma2(acc2[2][0], a2, w0); ffma2(acc2[2][1], a2, w1); ffma2(acc2[2][2], a2, w2); ffma2(acc2[2][3], a2, w3);
            ffma2(acc2[3][0], a3, w0); ffma2(acc2[3][1], a3, w1); ffma2(acc2[3][2], a3, w2); ffma2(acc2[3][3], a3, w3);
        }
#pragma unroll
        for (int a = 0; a < 4; a++) {
            ulonglong2* dst = reinterpret_cast<ulonglong2*>(&qs[(t0 + a) * 100 + oc]);
            dst[0] = make_ulonglong2(acc2[a][0], acc2[a][1]);
            dst[1] = make_ulonglong2(acc2[a][2], acc2[a][3]);
        }
    }
    __syncthreads();

    // ---- Phase C: banded attention, warp per token (lane = channel), conflict-free ----
    int warp = tid >> 5, lane = tid & 31;
    for (int rep = 0; rep < 9; rep++) {
        int tl = rep * 8 + warp;
        if (tl >= T_TILE) break;
        int f = fb + tl;
        if (f < F_N) {
            float qv = qs[tl * 100 + lane];
            float s[3];
#pragma unroll
            for (int j = 0; j < 3; j++) {
                float p = qv * qs[(tl + j) * 100 + 32 + lane];
                p += __shfl_xor_sync(0xffffffffu, p, 1);
                p += __shfl_xor_sync(0xffffffffu, p, 2);
                p += __shfl_xor_sync(0xffffffffu, p, 4);
                s[j] = (f + j < F_N) ? p * 0.35355339059327373f : -INFINITY;
            }
            float m = fmaxf(s[0], fmaxf(s[1], s[2]));
            float e0 = __expf(s[0] - m);
            float e1 = (f + 1 < F_N) ? __expf(s[1] - m) : 0.f;
            float e2 = (f + 2 < F_N) ? __expf(s[2] - m) : 0.f;
            float inv = 1.f / (e0 + e1 + e2);
            float ao = (e0 * qs[tl * 100 + 64 + lane]
                      + e1 * qs[(tl + 1) * 100 + 64 + lane]
                      + e2 * qs[(tl + 2) * 100 + 64 + lane]) * inv;
            as_[tl * 33 + lane] = ao;
        }
    }
    __syncthreads();

    // ---- Phase D: proj GEMM + BN/GELU conv path -> y (token-major), FFMA2 ----
#pragma unroll
    for (int tb = 0; tb < 2; tb++) {
        int tl = tb * 64 + (tid >> 2);
        int o0 = (tid & 3) << 3;
        if (tl < T_TILE) {
            int f = fb + tl;
            if (f < F_N) {
                u64 acc2[4];
                const u64* pb2 = reinterpret_cast<const u64*>(pb + o0);
                acc2[0] = pb2[0]; acc2[1] = pb2[1]; acc2[2] = pb2[2]; acc2[3] = pb2[3];
#pragma unroll
                for (int i = 0; i < 32; i++) {
                    u64 a2 = pack2(as_[tl * 33 + i]);
                    const u64* wr = reinterpret_cast<const u64*>(wp + i * 32 + o0);
                    ffma2(acc2[0], a2, wr[0]);
                    ffma2(acc2[1], a2, wr[1]);
                    ffma2(acc2[2], a2, wr[2]);
                    ffma2(acc2[3], a2, wr[3]);
                }
                const float4* cg = reinterpret_cast<const float4*>(&g_c[(rowbase + f) * 32 + o0]);
                float4 c0 = cg[0], c1 = cg[1];
                float cv[8] = {c0.x, c0.y, c0.z, c0.w, c1.x, c1.y, c1.z, c1.w};
                float yv[8];
#pragma unroll
                for (int k = 0; k < 4; k++) {
                    float2 pa = unpack2(acc2[k]);
                    float cn0 = cv[2 * k] * bna[o0 + 2 * k] + bnb[o0 + 2 * k];
                    float cn1 = cv[2 * k + 1] * bna[o0 + 2 * k + 1] + bnb[o0 + 2 * k + 1];
                    yv[2 * k] = gelu_f(cn0) + pa.x;
                    yv[2 * k + 1] = gelu_f(cn1) + pa.y;
                }
                float4* yo = reinterpret_cast<float4*>(&y[tl * 36 + o0]);
                yo[0] = make_float4(yv[0], yv[1], yv[2], yv[3]);
                yo[1] = make_float4(yv[4], yv[5], yv[6], yv[7]);
            }
        }
    }
    __syncthreads();

    // ---- Phase E: LayerNorm over channels, warp per token, conflict-free ----
    for (int rep = 0; rep < 9; rep++) {
        int tl = rep * 8 + warp;
        if (tl >= T_TILE) break;
        int f = fb + tl;
        if (f < F_N) {
            float yv = y[tl * 36 + lane];
            float s = yv;
#pragma unroll
            for (int off = 1; off < 32; off <<= 1) s += __shfl_xor_sync(0xffffffffu, s, off);
            float mean = s * (1.f / 32.f);
            float d = yv - mean;
            float v = d * d;
#pragma unroll
            for (int off = 1; off < 32; off <<= 1) v += __shfl_xor_sync(0xffffffffu, v, off);
            float o = d * rsqrtf(v * (1.f / 32.f) + 1e-5f) * lg[lane] + lb[lane];
            hdst[(rowbase + f) * 32 + lane] = o;
        }
    }
}

// ===================== head: gelu(h@W1+b1) @ W2 + b2 -> sigmoid =====================
__global__ __launch_bounds__(256) void k_head(const float* __restrict__ w1,
                                              const float* __restrict__ b1,
                                              const float* __restrict__ w2,
                                              const float* __restrict__ b2,
                                              float* __restrict__ out) {
    __shared__ __align__(16) float hsm[256][33];
    __shared__ __align__(16) float ws1[512];
    __shared__ __align__(16) float wb1[16];
    __shared__ __align__(16) float ws2[16];
    __shared__ float b2s;
    int t0 = blockIdx.x * 256;
    const float* hsrc = g_h[0];
    for (int idx = threadIdx.x; idx < 256 * 32; idx += 256) {
        int tok = idx >> 5, c = idx & 31;
        hsm[tok][c] = hsrc[(size_t)(t0 + tok) * 32 + c];
    }
    for (int idx = threadIdx.x; idx < 512; idx += 256) ws1[idx] = w1[idx];
    if (threadIdx.x < 16) { wb1[threadIdx.x] = b1[threadIdx.x]; ws2[threadIdx.x] = w2[threadIdx.x]; }
    if (threadIdx.x == 0) b2s = b2[0];
    __syncthreads();

    const float* hr = hsm[threadIdx.x];
    u64 s2[8];
    const u64* wb2 = reinterpret_cast<const u64*>(wb1);
#pragma unroll
    for (int k = 0; k < 8; k++) s2[k] = wb2[k];
#pragma unroll
    for (int i = 0; i < 32; i++) {
        u64 a2 = pack2(hr[i]);
        const u64* wr = reinterpret_cast<const u64*>(ws1 + i * 16);
#pragma unroll
        for (int k = 0; k < 8; k++) ffma2(s2[k], a2, wr[k]);
    }
    float m = b2s;
#pragma unroll
    for (int k = 0; k < 8; k++) {
        float2 f2 = unpack2(s2[k]);
        m += gelu_f(f2.x) * ws2[2 * k] + gelu_f(f2.y) * ws2[2 * k + 1];
    }
    out[t0 + threadIdx.x] = 1.f / (1.f + expf(-m));
}

// ===================== launcher =====================
extern "C" void kernel_launch(void* const* d_in, const int* in_sizes, int n_in,
                              void* d_out, int out_size) {
    const float* x      = (const float*)d_in[0];
    const float* in_w   = (const float*)d_in[1];
    const float* in_b   = (const float*)d_in[2];
    const float* conv_w = (const float*)d_in[3];
    const float* bn_g   = (const float*)d_in[4];
    const float* bn_b   = (const float*)d_in[5];
    const float* qkv_w  = (const float*)d_in[6];
    const float* proj_w = (const float*)d_in[7];
    const float* proj_b = (const float*)d_in[8];
    const float* ln_g   = (const float*)d_in[9];
    const float* ln_b   = (const float*)d_in[10];
    const float* h1_w   = (const float*)d_in[11];
    const float* h1_b   = (const float*)d_in[12];
    const float* h2_w   = (const float*)d_in[13];
    const float* h2_b   = (const float*)d_in[14];
    float* out = (float*)d_out;

    const int smem_apply = SMEM_APPLY_FLOATS * (int)sizeof(float);
    cudaFuncSetAttribute(k_apply, cudaFuncAttributeMaxDynamicSharedMemorySize, smem_apply);

    k_inproj<<<NTOKBLK, 256>>>(x, in_w, in_b);
    for (int l = 0; l < 4; l++) {
        int src = l & 1;
        k_conv<<<NCONVBLK, 256>>>(conv_w + l * 3072, src);
        k_bnfin<<<32, 256>>>(bn_g + l * 32, bn_b + l * 32);
        k_apply<<<dim3(4, 1024), 256, smem_apply>>>(qkv_w + l * 3072, proj_w + l * 1024,
                                                    proj_b + l * 32, ln_g + l * 32,
                                                    ln_b + l * 32, src);
    }
    k_head<<<NTOKBLK, 256>>>(h1_w, h1_b, h2_w, h2_b, out);
}